// round 1
// baseline (speedup 1.0000x reference)
#include <cuda_runtime.h>
#include <math.h>

#define TT 2048
#define DD 768
#define NH 12
#define DHH 64

// ---------------- scratch (static device globals; no allocs) ----------------
__device__ float g_xn[TT * DD];
__device__ float g_qkv[TT * 3 * DD];
__device__ float g_geov[TT * DD];
__device__ float g_rl[TT * NH * 6];
__device__ float g_jw[TT * NH * 6];
__device__ float g_gate[TT];
__device__ float g_comb[TT * DD];
__device__ float g_h[TT * DD];
__device__ float g_m2[TT * DD];
__device__ float g_fc[TT * 4 * DD];

// ---------------- LayerNorm ----------------
__global__ void ln_kernel(const float* __restrict__ x, const float* __restrict__ g,
                          const float* __restrict__ b, float* __restrict__ o) {
  int t = blockIdx.x;
  const float* xr = x + (size_t)t * DD;
  float s = 0.f, ss = 0.f;
  for (int i = threadIdx.x; i < DD; i += 256) { float v = xr[i]; s += v; ss += v * v; }
  __shared__ float rs[8], rss[8];
  for (int off = 16; off > 0; off >>= 1) {
    s  += __shfl_down_sync(0xffffffffu, s, off);
    ss += __shfl_down_sync(0xffffffffu, ss, off);
  }
  int wid = threadIdx.x >> 5, lid = threadIdx.x & 31;
  if (lid == 0) { rs[wid] = s; rss[wid] = ss; }
  __syncthreads();
  __shared__ float mu_s, rstd_s;
  if (threadIdx.x == 0) {
    float S = 0.f, SS = 0.f;
    for (int i = 0; i < 8; i++) { S += rs[i]; SS += rss[i]; }
    float mu = S / (float)DD;
    float var = SS / (float)DD - mu * mu;
    mu_s = mu;
    rstd_s = rsqrtf(var + 1e-5f);
  }
  __syncthreads();
  float mu = mu_s, rstd = rstd_s;
  for (int i = threadIdx.x; i < DD; i += 256)
    o[(size_t)t * DD + i] = (xr[i] - mu) * rstd * g[i] + b[i];
}

// ---------------- generic SGEMM: C = A@W + bias (+R) (+GELU) ----------------
// 128x128 block tile, KT=8, 256 threads, 8x8 micro-tile.
// M, N multiples of 128; K multiple of 8.
template<int GELU>
__global__ __launch_bounds__(256) void sgemm_kernel(
    const float* __restrict__ A, const float* __restrict__ W,
    const float* __restrict__ bias, const float* __restrict__ R,
    float* __restrict__ C, int M, int N, int K) {
  __shared__ float As[8][128];
  __shared__ float Bs[8][128];
  int tid = threadIdx.x;
  int row0 = blockIdx.y * 128, col0 = blockIdx.x * 128;
  int tx = tid & 15, ty = tid >> 4;
  float acc[8][8];
#pragma unroll
  for (int i = 0; i < 8; i++)
#pragma unroll
    for (int j = 0; j < 8; j++) acc[i][j] = 0.f;

  int arow = tid >> 1, ak = (tid & 1) << 2;
  int brow = tid >> 5, bcol = (tid & 31) << 2;
  const float* Ap = A + (size_t)(row0 + arow) * K + ak;
  const float* Wp = W + (size_t)brow * N + col0 + bcol;

  for (int kt = 0; kt < K; kt += 8) {
    float4 a4 = *(const float4*)Ap;
    float4 b4 = *(const float4*)Wp;
    As[ak + 0][arow] = a4.x; As[ak + 1][arow] = a4.y;
    As[ak + 2][arow] = a4.z; As[ak + 3][arow] = a4.w;
    *(float4*)&Bs[brow][bcol] = b4;
    __syncthreads();
#pragma unroll
    for (int kk = 0; kk < 8; kk++) {
      float a[8], b[8];
      *(float4*)(a)     = *(const float4*)&As[kk][ty * 4];
      *(float4*)(a + 4) = *(const float4*)&As[kk][64 + ty * 4];
      *(float4*)(b)     = *(const float4*)&Bs[kk][tx * 4];
      *(float4*)(b + 4) = *(const float4*)&Bs[kk][64 + tx * 4];
#pragma unroll
      for (int i = 0; i < 8; i++)
#pragma unroll
        for (int j = 0; j < 8; j++)
          acc[i][j] += a[i] * b[j];
    }
    __syncthreads();
    Ap += 8;
    Wp += (size_t)8 * N;
  }

#pragma unroll
  for (int ib = 0; ib < 2; ib++)
#pragma unroll
    for (int i = 0; i < 4; i++) {
      int r = row0 + ib * 64 + ty * 4 + i;
#pragma unroll
      for (int jb = 0; jb < 2; jb++) {
        int c = col0 + jb * 64 + tx * 4;
        float out[4];
#pragma unroll
        for (int j = 0; j < 4; j++) {
          float v = acc[ib * 4 + i][jb * 4 + j] + bias[c + j];
          if (R) v += R[(size_t)r * N + c + j];
          if (GELU) {
            float u = 0.7978845608028654f * (v + 0.044715f * v * v * v);
            v = 0.5f * v * (1.f + tanhf(u));
          }
          out[j] = v;
        }
        *(float4*)&C[(size_t)r * N + c] = *(float4*)out;
      }
    }
}

// ---------------- skinny projections + Plucker lines + gate ----------------
__global__ void lines_kernel(const float* __restrict__ xn,
                             const float* __restrict__ w1w, const float* __restrict__ w2w,
                             const float* __restrict__ w1r, const float* __restrict__ w2r,
                             const float* __restrict__ gw, const float* __restrict__ gb,
                             float* __restrict__ rl, float* __restrict__ jwout,
                             float* __restrict__ gate) {
  int t = blockIdx.x;
  __shared__ float xs[DD], xp[DD];
  __shared__ float proj[4 * 48 + 12];
  for (int i = threadIdx.x; i < DD; i += 256) {
    xs[i] = xn[(size_t)t * DD + i];
    xp[i] = (t == 0) ? 0.f : xn[(size_t)(t - 1) * DD + i];
  }
  __syncthreads();
  int tid = threadIdx.x;
  if (tid < 204) {
    float acc = 0.f;
    if (tid < 48) {
      int c = tid;
      for (int k = 0; k < DD; k++) acc += xp[k] * w1w[k * 48 + c];
      proj[tid] = acc;
    } else if (tid < 96) {
      int c = tid - 48;
      for (int k = 0; k < DD; k++) acc += xs[k] * w2w[k * 48 + c];
      proj[tid] = acc;
    } else if (tid < 144) {
      int c = tid - 96;
      for (int k = 0; k < DD; k++) acc += xs[k] * w1r[k * 48 + c];
      proj[tid] = acc;
    } else if (tid < 192) {
      int c = tid - 144;
      for (int k = 0; k < DD; k++) acc += xs[k] * w2r[k * 48 + c];
      proj[tid] = acc;
    } else {
      int c = tid - 192;
      for (int k = 0; k < DD; k++) acc += xs[k] * gw[k * 12 + c];
      proj[tid] = acc + gb[c];
    }
  }
  __syncthreads();
  if (tid < NH) {
    int h = tid;
    float a[4], b[4], L[6];
    // write lines -> apply J6 -> J_write = [L5, -L4, L3, L2, -L1, L0]
    for (int i = 0; i < 4; i++) { a[i] = proj[h * 4 + i]; b[i] = proj[48 + h * 4 + i]; }
    L[0] = a[0]*b[1] - a[1]*b[0];
    L[1] = a[0]*b[2] - a[2]*b[0];
    L[2] = a[0]*b[3] - a[3]*b[0];
    L[3] = a[1]*b[2] - a[2]*b[1];
    L[4] = a[1]*b[3] - a[3]*b[1];
    L[5] = a[2]*b[3] - a[3]*b[2];
    float n = sqrtf(L[0]*L[0]+L[1]*L[1]+L[2]*L[2]+L[3]*L[3]+L[4]*L[4]+L[5]*L[5]);
    float inv = 1.f / fmaxf(n, 1e-12f);
    float* jwp = jwout + ((size_t)t * NH + h) * 6;
    jwp[0] =  L[5] * inv;
    jwp[1] = -L[4] * inv;
    jwp[2] =  L[3] * inv;
    jwp[3] =  L[2] * inv;
    jwp[4] = -L[1] * inv;
    jwp[5] =  L[0] * inv;
    // read lines (normalized, stored directly)
    for (int i = 0; i < 4; i++) { a[i] = proj[96 + h * 4 + i]; b[i] = proj[144 + h * 4 + i]; }
    L[0] = a[0]*b[1] - a[1]*b[0];
    L[1] = a[0]*b[2] - a[2]*b[0];
    L[2] = a[0]*b[3] - a[3]*b[0];
    L[3] = a[1]*b[2] - a[2]*b[1];
    L[4] = a[1]*b[3] - a[3]*b[1];
    L[5] = a[2]*b[3] - a[3]*b[2];
    n = sqrtf(L[0]*L[0]+L[1]*L[1]+L[2]*L[2]+L[3]*L[3]+L[4]*L[4]+L[5]*L[5]);
    inv = 1.f / fmaxf(n, 1e-12f);
    float* rlp = rl + ((size_t)t * NH + h) * 6;
    for (int p = 0; p < 6; p++) rlp[p] = L[p] * inv;
  }
  if (tid == 0) {
    float s = 0.f;
    for (int i = 0; i < 12; i++) s += 1.f / (1.f + __expf(-proj[192 + i]));
    gate[t] = s / 12.f;
  }
}

// ---------------- fused dual-path causal flash attention ----------------
#define PADK 68
struct AttnSmem {
  float Qts[64][PADK];  // [d][r]  (Q transposed)
  float Kts[64][PADK];  // [d][c]
  float Vs[64][PADK];   // [c][d]
  float Gs[64][PADK];   // [c][d]  geo_v
  float Ss[64][PADK];   // std scores / probs
  float Sg[64][PADK];   // geo scores / probs
  float RLs[64][6];
  float JWs[64][6];
  float mst[64], lst[64], ast[64];
  float mgt[64], lgt[64], agt[64];
};

__global__ __launch_bounds__(256) void attn_kernel(
    const float* __restrict__ qkv, const float* __restrict__ geov,
    const float* __restrict__ rl, const float* __restrict__ jwg,
    const float* __restrict__ gate, const float* __restrict__ inc,
    float* __restrict__ comb) {
  extern __shared__ char smem_raw[];
  AttnSmem& S = *reinterpret_cast<AttnSmem*>(smem_raw);
  int qt = blockIdx.x, h = blockIdx.y;
  int q0 = qt * 64;
  int tid = threadIdx.x;
  int tx = tid & 15, ty = tid >> 4;
  int lr = tid >> 4;
  int ld = (tid & 15) << 2;
  float inch = inc[h];

  // load Q tile transposed
  for (int r = lr; r < 64; r += 16) {
    const float* p = qkv + (size_t)(q0 + r) * (3 * DD) + h * DHH + ld;
    float4 v = *(const float4*)p;
    S.Qts[ld + 0][r] = v.x; S.Qts[ld + 1][r] = v.y;
    S.Qts[ld + 2][r] = v.z; S.Qts[ld + 3][r] = v.w;
  }
  for (int i = tid; i < 64 * 6; i += 256) {
    int r = i / 6, p = i % 6;
    S.RLs[r][p] = rl[((size_t)(q0 + r) * NH + h) * 6 + p];
  }
  if (tid < 64) {
    S.mst[tid] = -1e30f; S.lst[tid] = 0.f;
    S.mgt[tid] = -1e30f; S.lgt[tid] = 0.f;
  }

  float Ost[4][4], Ogo[4][4];
#pragma unroll
  for (int i = 0; i < 4; i++)
#pragma unroll
    for (int j = 0; j < 4; j++) { Ost[i][j] = 0.f; Ogo[i][j] = 0.f; }

  for (int kt = 0; kt <= qt; kt++) {
    int s0 = kt * 64;
    for (int r = lr; r < 64; r += 16) {
      const float* pk = qkv + (size_t)(s0 + r) * (3 * DD) + DD + h * DHH + ld;
      float4 kv = *(const float4*)pk;
      S.Kts[ld + 0][r] = kv.x; S.Kts[ld + 1][r] = kv.y;
      S.Kts[ld + 2][r] = kv.z; S.Kts[ld + 3][r] = kv.w;
      const float* pv = qkv + (size_t)(s0 + r) * (3 * DD) + 2 * DD + h * DHH + ld;
      *(float4*)&S.Vs[r][ld] = *(const float4*)pv;
      const float* pg = geov + (size_t)(s0 + r) * DD + h * DHH + ld;
      *(float4*)&S.Gs[r][ld] = *(const float4*)pg;
    }
    for (int i = tid; i < 64 * 6; i += 256) {
      int r = i / 6, p = i % 6;
      S.JWs[r][p] = jwg[((size_t)(s0 + r) * NH + h) * 6 + p];
    }
    __syncthreads();

    // std logits: Q @ K^T
    float acc[4][4];
#pragma unroll
    for (int i = 0; i < 4; i++)
#pragma unroll
      for (int j = 0; j < 4; j++) acc[i][j] = 0.f;
#pragma unroll 4
    for (int d = 0; d < 64; d++) {
      float4 av = *(const float4*)&S.Qts[d][ty * 4];
      float4 bv = *(const float4*)&S.Kts[d][tx * 4];
      float a[4] = {av.x, av.y, av.z, av.w};
      float b[4] = {bv.x, bv.y, bv.z, bv.w};
#pragma unroll
      for (int i = 0; i < 4; i++)
#pragma unroll
        for (int j = 0; j < 4; j++) acc[i][j] += a[i] * b[j];
    }
    // geo logits: read_lines . J_write
    float gac[4][4];
#pragma unroll
    for (int i = 0; i < 4; i++)
#pragma unroll
      for (int j = 0; j < 4; j++) gac[i][j] = 0.f;
#pragma unroll
    for (int p = 0; p < 6; p++) {
      float a[4], b[4];
#pragma unroll
      for (int i = 0; i < 4; i++) a[i] = S.RLs[ty * 4 + i][p];
#pragma unroll
      for (int j = 0; j < 4; j++) b[j] = S.JWs[tx * 4 + j][p];
#pragma unroll
      for (int i = 0; i < 4; i++)
#pragma unroll
        for (int j = 0; j < 4; j++) gac[i][j] += a[i] * b[j];
    }
    bool diag = (kt == qt);
#pragma unroll
    for (int i = 0; i < 4; i++) {
      int r = ty * 4 + i;
#pragma unroll
      for (int j = 0; j < 4; j++) {
        int c = tx * 4 + j;
        float sv = acc[i][j] * 0.125f;   // DH^-0.5
        float gv = gac[i][j] * inch;
        if (diag && c > r) { sv = -1e30f; gv = -1e30f; }
        S.Ss[r][c] = sv;
        S.Sg[r][c] = gv;
      }
    }
    __syncthreads();

    // online softmax row pass (both paths), one thread per row
    if (tid < 64) {
      int r = tid;
      float mx = -1e30f;
      for (int c = 0; c < 64; c++) mx = fmaxf(mx, S.Ss[r][c]);
      float mo = S.mst[r];
      float mn = fmaxf(mo, mx);
      float al = __expf(mo - mn);
      float sum = 0.f;
      for (int c = 0; c < 64; c++) {
        float pv = __expf(S.Ss[r][c] - mn);
        S.Ss[r][c] = pv; sum += pv;
      }
      S.mst[r] = mn; S.lst[r] = S.lst[r] * al + sum; S.ast[r] = al;

      mx = -1e30f;
      for (int c = 0; c < 64; c++) mx = fmaxf(mx, S.Sg[r][c]);
      mo = S.mgt[r];
      mn = fmaxf(mo, mx);
      al = __expf(mo - mn);
      sum = 0.f;
      for (int c = 0; c < 64; c++) {
        float pv = __expf(S.Sg[r][c] - mn);
        S.Sg[r][c] = pv; sum += pv;
      }
      S.mgt[r] = mn; S.lgt[r] = S.lgt[r] * al + sum; S.agt[r] = al;
    }
    __syncthreads();

    // rescale accumulators + P@V for both paths
    float als[4], alg[4];
#pragma unroll
    for (int i = 0; i < 4; i++) { als[i] = S.ast[ty * 4 + i]; alg[i] = S.agt[ty * 4 + i]; }
#pragma unroll
    for (int i = 0; i < 4; i++)
#pragma unroll
      for (int j = 0; j < 4; j++) { Ost[i][j] *= als[i]; Ogo[i][j] *= alg[i]; }
#pragma unroll 4
    for (int c = 0; c < 64; c++) {
      float4 bv = *(const float4*)&S.Vs[c][tx * 4];
      float4 gv = *(const float4*)&S.Gs[c][tx * 4];
#pragma unroll
      for (int i = 0; i < 4; i++) {
        float as_ = S.Ss[ty * 4 + i][c];
        float ag_ = S.Sg[ty * 4 + i][c];
        Ost[i][0] += as_ * bv.x; Ost[i][1] += as_ * bv.y;
        Ost[i][2] += as_ * bv.z; Ost[i][3] += as_ * bv.w;
        Ogo[i][0] += ag_ * gv.x; Ogo[i][1] += ag_ * gv.y;
        Ogo[i][2] += ag_ * gv.z; Ogo[i][3] += ag_ * gv.w;
      }
    }
    __syncthreads();
  }

  // epilogue: normalize, gate-combine, store
#pragma unroll
  for (int i = 0; i < 4; i++) {
    int r = ty * 4 + i;
    int t = q0 + r;
    float g = gate[t];
    float is = 1.f / S.lst[r];
    float ig = 1.f / S.lgt[r];
    float o[4];
#pragma unroll
    for (int j = 0; j < 4; j++)
      o[j] = (1.f - g) * Ost[i][j] * is + g * Ogo[i][j] * ig;
    *(float4*)&comb[(size_t)t * DD + h * DHH + tx * 4] = *(float4*)o;
  }
}

// ---------------- launcher ----------------
extern "C" void kernel_launch(void* const* d_in, const int* in_sizes, int n_in,
                              void* d_out, int out_size) {
  const float* x      = (const float*)d_in[0];
  const float* ln1_g  = (const float*)d_in[1];
  const float* ln1_b  = (const float*)d_in[2];
  const float* qkv_w  = (const float*)d_in[3];
  const float* qkv_b  = (const float*)d_in[4];
  const float* w1w    = (const float*)d_in[5];
  const float* w2w    = (const float*)d_in[6];
  const float* w1r    = (const float*)d_in[7];
  const float* w2r    = (const float*)d_in[8];
  const float* geovw  = (const float*)d_in[9];
  const float* geovb  = (const float*)d_in[10];
  const float* gatew  = (const float*)d_in[11];
  const float* gateb  = (const float*)d_in[12];
  const float* incs   = (const float*)d_in[13];
  const float* outw   = (const float*)d_in[14];
  const float* outb   = (const float*)d_in[15];
  const float* ln2_g  = (const float*)d_in[16];
  const float* ln2_b  = (const float*)d_in[17];
  const float* fcw    = (const float*)d_in[18];
  const float* fcb    = (const float*)d_in[19];
  const float* projw  = (const float*)d_in[20];
  const float* projb  = (const float*)d_in[21];
  float* out = (float*)d_out;

  float *xn, *qkv, *geov, *rl, *jw, *gate, *comb, *hb, *m2, *fc;
  cudaGetSymbolAddress((void**)&xn,   g_xn);
  cudaGetSymbolAddress((void**)&qkv,  g_qkv);
  cudaGetSymbolAddress((void**)&geov, g_geov);
  cudaGetSymbolAddress((void**)&rl,   g_rl);
  cudaGetSymbolAddress((void**)&jw,   g_jw);
  cudaGetSymbolAddress((void**)&gate, g_gate);
  cudaGetSymbolAddress((void**)&comb, g_comb);
  cudaGetSymbolAddress((void**)&hb,   g_h);
  cudaGetSymbolAddress((void**)&m2,   g_m2);
  cudaGetSymbolAddress((void**)&fc,   g_fc);

  cudaFuncSetAttribute(attn_kernel, cudaFuncAttributeMaxDynamicSharedMemorySize,
                       (int)sizeof(AttnSmem));

  // 1. ln1
  ln_kernel<<<TT, 256>>>(x, ln1_g, ln1_b, xn);
  // 2. qkv projection (2048x768 @ 768x2304)
  sgemm_kernel<0><<<dim3(2304 / 128, TT / 128), 256>>>(xn, qkv_w, qkv_b, nullptr, qkv,
                                                       TT, 2304, DD);
  // 3. geo_v projection
  sgemm_kernel<0><<<dim3(DD / 128, TT / 128), 256>>>(xn, geovw, geovb, nullptr, geov,
                                                     TT, DD, DD);
  // 4. lines + gate
  lines_kernel<<<TT, 256>>>(xn, w1w, w2w, w1r, w2r, gatew, gateb, rl, jw, gate);
  // 5. dual-path attention
  attn_kernel<<<dim3(TT / 64, NH), 256, sizeof(AttnSmem)>>>(qkv, geov, rl, jw, gate,
                                                            incs, comb);
  // 6. out projection + residual x -> h
  sgemm_kernel<0><<<dim3(DD / 128, TT / 128), 256>>>(comb, outw, outb, x, hb,
                                                     TT, DD, DD);
  // 7. ln2
  ln_kernel<<<TT, 256>>>(hb, ln2_g, ln2_b, m2);
  // 8. fc + gelu
  sgemm_kernel<1><<<dim3(4 * DD / 128, TT / 128), 256>>>(m2, fcw, fcb, nullptr, fc,
                                                         TT, 4 * DD, DD);
  // 9. proj + residual h -> out
  sgemm_kernel<0><<<dim3(DD / 128, TT / 128), 256>>>(fc, projw, projb, hb, out,
                                                     TT, DD, 4 * DD);
}

// round 6
// speedup vs baseline: 1.9258x; 1.9258x over previous
#include <cuda_runtime.h>
#include <math.h>
#include <stdint.h>

#define TT 2048
#define DD 768
#define NH 12
#define DHH 64

// ---------------- scratch (static device globals; no allocs) ----------------
__device__ float g_xn[TT * DD];
__device__ float g_qkv[TT * 3 * DD];
__device__ float g_geov[TT * DD];
__device__ float g_rl[TT * NH * 6];
__device__ float g_jw[TT * NH * 6];
__device__ float g_gate[TT];
__device__ float g_comb[TT * DD];
__device__ float g_h[TT * DD];
__device__ float g_m2[TT * DD];
__device__ float g_fc[TT * 4 * DD];
__device__ float g_wcat[DD * 256];
__device__ float g_proj[TT * 256];

// ---------------- helpers ----------------
__device__ __forceinline__ uint32_t f2tf32(float f) {
  uint32_t u;
  asm("cvt.rna.tf32.f32 %0, %1;" : "=r"(u) : "f"(f));
  return u;
}

__device__ __forceinline__ void mma_tf32(float* c, const uint32_t* a, const uint32_t* b) {
  asm volatile(
      "mma.sync.aligned.m16n8k8.row.col.f32.tf32.tf32.f32 "
      "{%0,%1,%2,%3}, {%4,%5,%6,%7}, {%8,%9}, {%0,%1,%2,%3};"
      : "+f"(c[0]), "+f"(c[1]), "+f"(c[2]), "+f"(c[3])
      : "r"(a[0]), "r"(a[1]), "r"(a[2]), "r"(a[3]), "r"(b[0]), "r"(b[1]));
}

// ---------------- LayerNorm ----------------
__global__ void ln_kernel(const float* __restrict__ x, const float* __restrict__ g,
                          const float* __restrict__ b, float* __restrict__ o) {
  int t = blockIdx.x;
  const float* xr = x + (size_t)t * DD;
  float s = 0.f, ss = 0.f;
  for (int i = threadIdx.x; i < DD; i += 256) { float v = xr[i]; s += v; ss += v * v; }
  __shared__ float rs[8], rss[8];
  for (int off = 16; off > 0; off >>= 1) {
    s  += __shfl_down_sync(0xffffffffu, s, off);
    ss += __shfl_down_sync(0xffffffffu, ss, off);
  }
  int wid = threadIdx.x >> 5, lid = threadIdx.x & 31;
  if (lid == 0) { rs[wid] = s; rss[wid] = ss; }
  __syncthreads();
  __shared__ float mu_s, rstd_s;
  if (threadIdx.x == 0) {
    float S = 0.f, SS = 0.f;
    for (int i = 0; i < 8; i++) { S += rs[i]; SS += rss[i]; }
    float mu = S / (float)DD;
    float var = SS / (float)DD - mu * mu;
    mu_s = mu;
    rstd_s = rsqrtf(var + 1e-5f);
  }
  __syncthreads();
  float mu = mu_s, rstd = rstd_s;
  for (int i = threadIdx.x; i < DD; i += 256)
    o[(size_t)t * DD + i] = (xr[i] - mu) * rstd * g[i] + b[i];
}

// ---------------- TF32 tensor-core GEMM ----------------
// C[M,N] = A[M,K] @ W[K,N] (+bias)(+R)(+GELU)
// 128x128 block tile, BK=16, 256 threads, warp tile 64x32, mma m16n8k8 tf32.
// EPI: 0=bias, 1=bias+residual, 2=bias+gelu, 3=plain
template<int EPI>
__global__ __launch_bounds__(256, 2) void mma_gemm(
    const float* __restrict__ A, const float* __restrict__ W,
    const float* __restrict__ bias, const float* __restrict__ R,
    float* __restrict__ C, int M, int N, int K) {
  __shared__ uint32_t As[2][16][132];
  __shared__ uint32_t Bs[2][16][132];
  int tid = threadIdx.x;
  int lane = tid & 31;
  int wid = tid >> 5;
  int wm = (wid >> 2) * 64, wn = (wid & 3) * 32;
  int gid = lane >> 2, tig = lane & 3;
  int row0 = blockIdx.y * 128, col0 = blockIdx.x * 128;

  float acc[4][4][4];
#pragma unroll
  for (int mi = 0; mi < 4; mi++)
#pragma unroll
    for (int ni = 0; ni < 4; ni++)
#pragma unroll
      for (int r = 0; r < 4; r++) acc[mi][ni][r] = 0.f;

  int arow = tid >> 2, acol = (tid & 3) << 2;
  int brow = tid >> 5, bcol = (tid & 31) << 2;
  const float* Abase = A + (size_t)(row0 + arow) * K + acol;
  const float* Wbase = W + (size_t)brow * N + col0 + bcol;

  int KT = K >> 4;
  float4 ra0, ra1, rb0, rb1;
  // preload tile 0
  ra0 = *(const float4*)(Abase);
  ra1 = *(const float4*)(Abase + (size_t)64 * K);
  rb0 = *(const float4*)(Wbase);
  rb1 = *(const float4*)(Wbase + (size_t)8 * N);
  {
    const float* a0p = &ra0.x; const float* a1p = &ra1.x;
#pragma unroll
    for (int i = 0; i < 4; i++) {
      As[0][acol + i][arow]      = f2tf32(a0p[i]);
      As[0][acol + i][arow + 64] = f2tf32(a1p[i]);
    }
    uint4 b0 = {f2tf32(rb0.x), f2tf32(rb0.y), f2tf32(rb0.z), f2tf32(rb0.w)};
    uint4 b1 = {f2tf32(rb1.x), f2tf32(rb1.y), f2tf32(rb1.z), f2tf32(rb1.w)};
    *(uint4*)&Bs[0][brow][bcol] = b0;
    *(uint4*)&Bs[0][brow + 8][bcol] = b1;
  }
  __syncthreads();

  int buf = 0;
  for (int kt = 0; kt < KT; kt++) {
    if (kt + 1 < KT) {
      const float* Ap = Abase + (kt + 1) * 16;
      const float* Wp = Wbase + (size_t)(kt + 1) * 16 * N;
      ra0 = *(const float4*)(Ap);
      ra1 = *(const float4*)(Ap + (size_t)64 * K);
      rb0 = *(const float4*)(Wp);
      rb1 = *(const float4*)(Wp + (size_t)8 * N);
    }
#pragma unroll
    for (int ks = 0; ks < 2; ks++) {
      uint32_t af[4][4];
#pragma unroll
      for (int mi = 0; mi < 4; mi++) {
        int r = wm + mi * 16 + gid;
        af[mi][0] = As[buf][ks * 8 + tig][r];
        af[mi][1] = As[buf][ks * 8 + tig][r + 8];
        af[mi][2] = As[buf][ks * 8 + tig + 4][r];
        af[mi][3] = As[buf][ks * 8 + tig + 4][r + 8];
      }
      uint32_t bf[4][2];
#pragma unroll
      for (int ni = 0; ni < 4; ni++) {
        int c = wn + ni * 8 + gid;
        bf[ni][0] = Bs[buf][ks * 8 + tig][c];
        bf[ni][1] = Bs[buf][ks * 8 + tig + 4][c];
      }
#pragma unroll
      for (int mi = 0; mi < 4; mi++)
#pragma unroll
        for (int ni = 0; ni < 4; ni++)
          mma_tf32(acc[mi][ni], af[mi], bf[ni]);
    }
    if (kt + 1 < KT) {
      int nb = buf ^ 1;
      const float* a0p = &ra0.x; const float* a1p = &ra1.x;
#pragma unroll
      for (int i = 0; i < 4; i++) {
        As[nb][acol + i][arow]      = f2tf32(a0p[i]);
        As[nb][acol + i][arow + 64] = f2tf32(a1p[i]);
      }
      uint4 b0 = {f2tf32(rb0.x), f2tf32(rb0.y), f2tf32(rb0.z), f2tf32(rb0.w)};
      uint4 b1 = {f2tf32(rb1.x), f2tf32(rb1.y), f2tf32(rb1.z), f2tf32(rb1.w)};
      *(uint4*)&Bs[nb][brow][bcol] = b0;
      *(uint4*)&Bs[nb][brow + 8][bcol] = b1;
    }
    __syncthreads();
    buf ^= 1;
  }

  // epilogue
#pragma unroll
  for (int mi = 0; mi < 4; mi++) {
#pragma unroll
    for (int ni = 0; ni < 4; ni++) {
      int r = row0 + wm + mi * 16 + gid;
      int c = col0 + wn + ni * 8 + tig * 2;
      float2 bv = {0.f, 0.f};
      if (EPI != 3) bv = *(const float2*)&bias[c];
#pragma unroll
      for (int half = 0; half < 2; half++) {
        int rr = r + half * 8;
        float v0 = acc[mi][ni][half * 2 + 0] + bv.x;
        float v1 = acc[mi][ni][half * 2 + 1] + bv.y;
        if (EPI == 1) {
          float2 rv = *(const float2*)&R[(size_t)rr * N + c];
          v0 += rv.x; v1 += rv.y;
        }
        if (EPI == 2) {
          float u0 = 0.7978845608028654f * (v0 + 0.044715f * v0 * v0 * v0);
          v0 = 0.5f * v0 * (1.f + tanhf(u0));
          float u1 = 0.7978845608028654f * (v1 + 0.044715f * v1 * v1 * v1);
          v1 = 0.5f * v1 * (1.f + tanhf(u1));
        }
        float2 ov = {v0, v1};
        *(float2*)&C[(size_t)rr * N + c] = ov;
      }
    }
  }
}

// ---------------- pack skinny weights into one 768x256 matrix ----------------
__global__ void pack_kernel(const float* __restrict__ w1w, const float* __restrict__ w2w,
                            const float* __restrict__ w1r, const float* __restrict__ w2r,
                            const float* __restrict__ gw, float* __restrict__ wcat) {
  int idx = blockIdx.x * 256 + threadIdx.x;
  if (idx >= DD * 256) return;
  int k = idx >> 8, c = idx & 255;
  float v = 0.f;
  if (c < 48)       v = w1w[k * 48 + c];
  else if (c < 96)  v = w2w[k * 48 + (c - 48)];
  else if (c < 144) v = w1r[k * 48 + (c - 96)];
  else if (c < 192) v = w2r[k * 48 + (c - 144)];
  else if (c < 204) v = gw[k * 12 + (c - 192)];
  wcat[idx] = v;
}

// ---------------- finish: exterior products from proj buffer ----------------
__global__ void lines_finish_kernel(const float* __restrict__ proj,
                                    float* __restrict__ rl, float* __restrict__ jwout) {
  int idx = blockIdx.x * 256 + threadIdx.x;
  if (idx >= TT * NH) return;
  int t = idx / NH, h = idx % NH;
  const float* pr = proj + (size_t)t * 256;
  float a[4], b[4], L[6];
  // write lines: a = proj[t-1, w1 part], b = proj[t, w2 part]
  for (int i = 0; i < 4; i++) {
    a[i] = (t == 0) ? 0.f : proj[(size_t)(t - 1) * 256 + h * 4 + i];
    b[i] = pr[48 + h * 4 + i];
  }
  L[0] = a[0]*b[1] - a[1]*b[0];
  L[1] = a[0]*b[2] - a[2]*b[0];
  L[2] = a[0]*b[3] - a[3]*b[0];
  L[3] = a[1]*b[2] - a[2]*b[1];
  L[4] = a[1]*b[3] - a[3]*b[1];
  L[5] = a[2]*b[3] - a[3]*b[2];
  float n = sqrtf(L[0]*L[0]+L[1]*L[1]+L[2]*L[2]+L[3]*L[3]+L[4]*L[4]+L[5]*L[5]);
  float inv = 1.f / fmaxf(n, 1e-12f);
  float* jwp = jwout + ((size_t)t * NH + h) * 6;
  jwp[0] =  L[5] * inv;
  jwp[1] = -L[4] * inv;
  jwp[2] =  L[3] * inv;
  jwp[3] =  L[2] * inv;
  jwp[4] = -L[1] * inv;
  jwp[5] =  L[0] * inv;
  // read lines
  for (int i = 0; i < 4; i++) { a[i] = pr[96 + h * 4 + i]; b[i] = pr[144 + h * 4 + i]; }
  L[0] = a[0]*b[1] - a[1]*b[0];
  L[1] = a[0]*b[2] - a[2]*b[0];
  L[2] = a[0]*b[3] - a[3]*b[0];
  L[3] = a[1]*b[2] - a[2]*b[1];
  L[4] = a[1]*b[3] - a[3]*b[1];
  L[5] = a[2]*b[3] - a[3]*b[2];
  n = sqrtf(L[0]*L[0]+L[1]*L[1]+L[2]*L[2]+L[3]*L[3]+L[4]*L[4]+L[5]*L[5]);
  inv = 1.f / fmaxf(n, 1e-12f);
  float* rlp = rl + ((size_t)t * NH + h) * 6;
  for (int p = 0; p < 6; p++) rlp[p] = L[p] * inv;
}

__global__ void gate_kernel(const float* __restrict__ proj, const float* __restrict__ gb,
                            float* __restrict__ gate) {
  int t = blockIdx.x * 256 + threadIdx.x;
  if (t >= TT) return;
  const float* pr = proj + (size_t)t * 256 + 192;
  float s = 0.f;
  for (int i = 0; i < 12; i++) s += 1.f / (1.f + __expf(-(pr[i] + gb[i])));
  gate[t] = s / 12.f;
}

// ---------------- fused dual-path causal flash attention ----------------
#define PADK 68
struct AttnSmem {
  float Qts[64][PADK];  // [d][r]  (Q transposed)
  float Kts[64][PADK];  // [d][c]
  float Vs[64][PADK];   // [c][d]
  float Gs[64][PADK];   // [c][d]  geo_v
  float Ss[64][PADK];   // std scores / probs
  float Sg[64][PADK];   // geo scores / probs
  float RLs[64][6];
  float JWs[64][6];
  float mst[64], lst[64], ast[64];
  float mgt[64], lgt[64], agt[64];
};

__global__ __launch_bounds__(256) void attn_kernel(
    const float* __restrict__ qkv, const float* __restrict__ geov,
    const float* __restrict__ rl, const float* __restrict__ jwg,
    const float* __restrict__ gate, const float* __restrict__ inc,
    float* __restrict__ comb) {
  extern __shared__ char smem_raw[];
  AttnSmem& S = *reinterpret_cast<AttnSmem*>(smem_raw);
  int qt = blockIdx.x, h = blockIdx.y;
  int q0 = qt * 64;
  int tid = threadIdx.x;
  int tx = tid & 15, ty = tid >> 4;
  int lr = tid >> 4;
  int ld = (tid & 15) << 2;
  float inch = inc[h];

  for (int r = lr; r < 64; r += 16) {
    const float* p = qkv + (size_t)(q0 + r) * (3 * DD) + h * DHH + ld;
    float4 v = *(const float4*)p;
    S.Qts[ld + 0][r] = v.x; S.Qts[ld + 1][r] = v.y;
    S.Qts[ld + 2][r] = v.z; S.Qts[ld + 3][r] = v.w;
  }
  for (int i = tid; i < 64 * 6; i += 256) {
    int r = i / 6, p = i % 6;
    S.RLs[r][p] = rl[((size_t)(q0 + r) * NH + h) * 6 + p];
  }
  if (tid < 64) {
    S.mst[tid] = -1e30f; S.lst[tid] = 0.f;
    S.mgt[tid] = -1e30f; S.lgt[tid] = 0.f;
  }

  float Ost[4][4], Ogo[4][4];
#pragma unroll
  for (int i = 0; i < 4; i++)
#pragma unroll
    for (int j = 0; j < 4; j++) { Ost[i][j] = 0.f; Ogo[i][j] = 0.f; }

  int srow = tid >> 2, sq = tid & 3;
  int sc0 = sq * 16;

  for (int kt = 0; kt <= qt; kt++) {
    int s0 = kt * 64;
    for (int r = lr; r < 64; r += 16) {
      const float* pk = qkv + (size_t)(s0 + r) * (3 * DD) + DD + h * DHH + ld;
      float4 kv = *(const float4*)pk;
      S.Kts[ld + 0][r] = kv.x; S.Kts[ld + 1][r] = kv.y;
      S.Kts[ld + 2][r] = kv.z; S.Kts[ld + 3][r] = kv.w;
      const float* pv = qkv + (size_t)(s0 + r) * (3 * DD) + 2 * DD + h * DHH + ld;
      *(float4*)&S.Vs[r][ld] = *(const float4*)pv;
      const float* pg = geov + (size_t)(s0 + r) * DD + h * DHH + ld;
      *(float4*)&S.Gs[r][ld] = *(const float4*)pg;
    }
    for (int i = tid; i < 64 * 6; i += 256) {
      int r = i / 6, p = i % 6;
      S.JWs[r][p] = jwg[((size_t)(s0 + r) * NH + h) * 6 + p];
    }
    __syncthreads();

    float acc[4][4];
#pragma unroll
    for (int i = 0; i < 4; i++)
#pragma unroll
      for (int j = 0; j < 4; j++) acc[i][j] = 0.f;
#pragma unroll 4
    for (int d = 0; d < 64; d++) {
      float4 av = *(const float4*)&S.Qts[d][ty * 4];
      float4 bv = *(const float4*)&S.Kts[d][tx * 4];
      float a[4] = {av.x, av.y, av.z, av.w};
      float b[4] = {bv.x, bv.y, bv.z, bv.w};
#pragma unroll
      for (int i = 0; i < 4; i++)
#pragma unroll
        for (int j = 0; j < 4; j++) acc[i][j] += a[i] * b[j];
    }
    float gac[4][4];
#pragma unroll
    for (int i = 0; i < 4; i++)
#pragma unroll
      for (int j = 0; j < 4; j++) gac[i][j] = 0.f;
#pragma unroll
    for (int p = 0; p < 6; p++) {
      float a[4], b[4];
#pragma unroll
      for (int i = 0; i < 4; i++) a[i] = S.RLs[ty * 4 + i][p];
#pragma unroll
      for (int j = 0; j < 4; j++) b[j] = S.JWs[tx * 4 + j][p];
#pragma unroll
      for (int i = 0; i < 4; i++)
#pragma unroll
        for (int j = 0; j < 4; j++) gac[i][j] += a[i] * b[j];
    }
    bool diag = (kt == qt);
#pragma unroll
    for (int i = 0; i < 4; i++) {
      int r = ty * 4 + i;
#pragma unroll
      for (int j = 0; j < 4; j++) {
        int c = tx * 4 + j;
        float sv = acc[i][j] * 0.125f;
        float gv = gac[i][j] * inch;
        if (diag && c > r) { sv = -1e30f; gv = -1e30f; }
        S.Ss[r][c] = sv;
        S.Sg[r][c] = gv;
      }
    }
    __syncthreads();

    // online softmax: 4 lanes per row (lanes of the same quad within a warp)
    {
      // --- std path ---
      float mx = -1e30f;
#pragma unroll
      for (int c = 0; c < 16; c++) mx = fmaxf(mx, S.Ss[srow][sc0 + c]);
      mx = fmaxf(mx, __shfl_xor_sync(0xffffffffu, mx, 1));
      mx = fmaxf(mx, __shfl_xor_sync(0xffffffffu, mx, 2));
      float mo = S.mst[srow];
      float mn = fmaxf(mo, mx);
      float sum = 0.f;
#pragma unroll
      for (int c = 0; c < 16; c++) {
        float pv = __expf(S.Ss[srow][sc0 + c] - mn);
        S.Ss[srow][sc0 + c] = pv; sum += pv;
      }
      sum += __shfl_xor_sync(0xffffffffu, sum, 1);
      sum += __shfl_xor_sync(0xffffffffu, sum, 2);
      if (sq == 0) {
        float al = __expf(mo - mn);
        S.mst[srow] = mn; S.lst[srow] = S.lst[srow] * al + sum; S.ast[srow] = al;
      }
      // --- geo path ---
      mx = -1e30f;
#pragma unroll
      for (int c = 0; c < 16; c++) mx = fmaxf(mx, S.Sg[srow][sc0 + c]);
      mx = fmaxf(mx, __shfl_xor_sync(0xffffffffu, mx, 1));
      mx = fmaxf(mx, __shfl_xor_sync(0xffffffffu, mx, 2));
      mo = S.mgt[srow];
      mn = fmaxf(mo, mx);
      sum = 0.f;
#pragma unroll
      for (int c = 0; c < 16; c++) {
        float pv = __expf(S.Sg[srow][sc0 + c] - mn);
        S.Sg[srow][sc0 + c] = pv; sum += pv;
      }
      sum += __shfl_xor_sync(0xffffffffu, sum, 1);
      sum += __shfl_xor_sync(0xffffffffu, sum, 2);
      if (sq == 0) {
        float al = __expf(mo - mn);
        S.mgt[srow] = mn; S.lgt[srow] = S.lgt[srow] * al + sum; S.agt[srow] = al;
      }
    }
    __syncthreads();

    float als[4], alg[4];
#pragma unroll
    for (int i = 0; i < 4; i++) { als[i] = S.ast[ty * 4 + i]; alg[i] = S.agt[ty * 4 + i]; }
#pragma unroll
    for (int i = 0; i < 4; i++)
#pragma unroll
      for (int j = 0; j < 4; j++) { Ost[i][j] *= als[i]; Ogo[i][j] *= alg[i]; }
#pragma unroll 4
    for (int c = 0; c < 64; c++) {
      float4 bv = *(const float4*)&S.Vs[c][tx * 4];
      float4 gv = *(const float4*)&S.Gs[c][tx * 4];
#pragma unroll
      for (int i = 0; i < 4; i++) {
        float as_ = S.Ss[ty * 4 + i][c];
        float ag_ = S.Sg[ty * 4 + i][c];
        Ost[i][0] += as_ * bv.x; Ost[i][1] += as_ * bv.y;
        Ost[i][2] += as_ * bv.z; Ost[i][3] += as_ * bv.w;
        Ogo[i][0] += ag_ * gv.x; Ogo[i][1] += ag_ * gv.y;
        Ogo[i][2] += ag_ * gv.z; Ogo[i][3] += ag_ * gv.w;
      }
    }
    __syncthreads();
  }

#pragma unroll
  for (int i = 0; i < 4; i++) {
    int r = ty * 4 + i;
    int t = q0 + r;
    float g = gate[t];
    float is = 1.f / S.lst[r];
    float ig = 1.f / S.lgt[r];
    float o[4];
#pragma unroll
    for (int j = 0; j < 4; j++)
      o[j] = (1.f - g) * Ost[i][j] * is + g * Ogo[i][j] * ig;
    *(float4*)&comb[(size_t)t * DD + h * DHH + tx * 4] = *(float4*)o;
  }
}

// ---------------- launcher ----------------
extern "C" void kernel_launch(void* const* d_in, const int* in_sizes, int n_in,
                              void* d_out, int out_size) {
  const float* x      = (const float*)d_in[0];
  const float* ln1_g  = (const float*)d_in[1];
  const float* ln1_b  = (const float*)d_in[2];
  const float* qkv_w  = (const float*)d_in[3];
  const float* qkv_b  = (const float*)d_in[4];
  const float* w1w    = (const float*)d_in[5];
  const float* w2w    = (const float*)d_in[6];
  const float* w1r    = (const float*)d_in[7];
  const float* w2r    = (const float*)d_in[8];
  const float* geovw  = (const float*)d_in[9];
  const float* geovb  = (const float*)d_in[10];
  const float* gatew  = (const float*)d_in[11];
  const float* gateb  = (const float*)d_in[12];
  const float* incs   = (const float*)d_in[13];
  const float* outw   = (const float*)d_in[14];
  const float* outb   = (const float*)d_in[15];
  const float* ln2_g  = (const float*)d_in[16];
  const float* ln2_b  = (const float*)d_in[17];
  const float* fcw    = (const float*)d_in[18];
  const float* fcb    = (const float*)d_in[19];
  const float* projw  = (const float*)d_in[20];
  const float* projb  = (const float*)d_in[21];
  float* out = (float*)d_out;

  float *xn, *qkv, *geov, *rl, *jw, *gate, *comb, *hb, *m2, *fc, *wcat, *proj;
  cudaGetSymbolAddress((void**)&xn,   g_xn);
  cudaGetSymbolAddress((void**)&qkv,  g_qkv);
  cudaGetSymbolAddress((void**)&geov, g_geov);
  cudaGetSymbolAddress((void**)&rl,   g_rl);
  cudaGetSymbolAddress((void**)&jw,   g_jw);
  cudaGetSymbolAddress((void**)&gate, g_gate);
  cudaGetSymbolAddress((void**)&comb, g_comb);
  cudaGetSymbolAddress((void**)&hb,   g_h);
  cudaGetSymbolAddress((void**)&m2,   g_m2);
  cudaGetSymbolAddress((void**)&fc,   g_fc);
  cudaGetSymbolAddress((void**)&wcat, g_wcat);
  cudaGetSymbolAddress((void**)&proj, g_proj);

  cudaFuncSetAttribute(attn_kernel, cudaFuncAttributeMaxDynamicSharedMemorySize,
                       (int)sizeof(AttnSmem));

  // 1. ln1
  ln_kernel<<<TT, 256>>>(x, ln1_g, ln1_b, xn);
  // 2. pack skinny weights (independent of ln; cheap)
  pack_kernel<<<(DD * 256 + 255) / 256, 256>>>(w1w, w2w, w1r, w2r, gatew, wcat);
  // 3. qkv projection
  mma_gemm<0><<<dim3(2304 / 128, TT / 128), 256>>>(xn, qkv_w, qkv_b, nullptr, qkv,
                                                   TT, 2304, DD);
  // 4. geo_v projection
  mma_gemm<0><<<dim3(DD / 128, TT / 128), 256>>>(xn, geovw, geovb, nullptr, geov,
                                                 TT, DD, DD);
  // 5. skinny projections via GEMM
  mma_gemm<3><<<dim3(256 / 128, TT / 128), 256>>>(xn, wcat, nullptr, nullptr, proj,
                                                  TT, 256, DD);
  // 6. lines + gate finish
  lines_finish_kernel<<<(TT * NH + 255) / 256, 256>>>(proj, rl, jw);
  gate_kernel<<<(TT + 255) / 256, 256>>>(proj, gateb, gate);
  // 7. dual-path attention
  attn_kernel<<<dim3(TT / 64, NH), 256, sizeof(AttnSmem)>>>(qkv, geov, rl, jw, gate,
                                                            incs, comb);
  // 8. out projection + residual x -> h
  mma_gemm<1><<<dim3(DD / 128, TT / 128), 256>>>(comb, outw, outb, x, hb,
                                                 TT, DD, DD);
  // 9. ln2
  ln_kernel<<<TT, 256>>>(hb, ln2_g, ln2_b, m2);
  // 10. fc + gelu
  mma_gemm<2><<<dim3(4 * DD / 128, TT / 128), 256>>>(m2, fcw, fcb, nullptr, fc,
                                                     TT, 4 * DD, DD);
  // 11. proj + residual h -> out
  mma_gemm<1><<<dim3(DD / 128, TT / 128), 256>>>(fc, projw, projb, hb, out,
                                                 TT, DD, 4 * DD);
}